// round 1
// baseline (speedup 1.0000x reference)
#include <cuda_runtime.h>
#include <cuda_bf16.h>
#include <math.h>

#define N_NODES 50000
#define N_EDGES 800000
#define FEAT 128

// ---------------- scratch (device globals: no allocations allowed) ----------
__device__ float g_f1[N_NODES * FEAT];     // x @ W1
__device__ float g_hres[N_NODES * FEAT];   // x @ Wp + bp
__device__ float g_h[N_NODES * FEAT];      // layer-1 output
__device__ float g_f2[N_NODES * FEAT];     // h @ W2
__device__ float g_el1[N_NODES * 2];
__device__ float g_er1[N_NODES * 2];
__device__ float g_el2[N_NODES];
__device__ float g_er2[N_NODES];
__device__ int   g_rowptr[N_NODES + 1];
__device__ int   g_cnt[N_NODES];
__device__ int   g_ssrc[N_EDGES];          // src ids sorted by dst

// ---------------- CSR build -------------------------------------------------
__global__ void zero_cnt_kernel() {
    int i = blockIdx.x * blockDim.x + threadIdx.x;
    if (i < N_NODES) g_cnt[i] = 0;
}

__global__ void count_kernel(const int* __restrict__ dst) {
    int e = blockIdx.x * blockDim.x + threadIdx.x;
    if (e < N_EDGES) atomicAdd(&g_cnt[dst[e]], 1);
}

__global__ void scan_kernel() {
    __shared__ int sh[1024];
    const int t = threadIdx.x;
    const int CH = (N_NODES + 1023) / 1024;   // 49
    int base = t * CH;
    int s = 0;
    for (int i = 0; i < CH; i++) {
        int idx = base + i;
        if (idx < N_NODES) s += g_cnt[idx];
    }
    sh[t] = s;
    __syncthreads();
    for (int off = 1; off < 1024; off <<= 1) {
        int v = (t >= off) ? sh[t - off] : 0;
        __syncthreads();
        sh[t] += v;
        __syncthreads();
    }
    int run = sh[t] - s;      // exclusive prefix
    for (int i = 0; i < CH; i++) {
        int idx = base + i;
        if (idx < N_NODES) {
            g_rowptr[idx] = run;
            run += g_cnt[idx];
            g_cnt[idx] = 0;   // reset -> used as cursor in fill_kernel
        }
    }
    if (t == 1023) g_rowptr[N_NODES] = sh[1023];
}

__global__ void fill_kernel(const int* __restrict__ src, const int* __restrict__ dst) {
    int e = blockIdx.x * blockDim.x + threadIdx.x;
    if (e < N_EDGES) {
        int d = dst[e];
        int pos = g_rowptr[d] + atomicAdd(&g_cnt[d], 1);
        g_ssrc[pos] = src[e];
    }
}

// ---------------- GEMM: C[n,128] = A[n,128] @ W[128,128] (+bias) ------------
// 128 threads/block, 64 rows x 128 cols per block, 8x8 microtiles.
__global__ void __launch_bounds__(128) gemm128_kernel(
    const float* __restrict__ A, const float* __restrict__ W,
    const float* __restrict__ bias, float* __restrict__ C, int nrows)
{
    __shared__ float xs[64][128];   // 32 KB: full K for 64 rows
    __shared__ float ws[32][128];   // 16 KB: K-chunk of W

    const int tid = threadIdx.x;
    const int row0 = blockIdx.x * 64;
    const int ty = tid >> 4;        // 0..7
    const int tx = tid & 15;        // 0..15

    // stage x tile
    #pragma unroll
    for (int i = 0; i < 16; i++) {
        int f4 = tid + i * 128;                 // 0..2047 float4s
        int r = f4 >> 5, c4 = (f4 & 31) << 2;
        float4 v = make_float4(0.f, 0.f, 0.f, 0.f);
        if (row0 + r < nrows) v = *(const float4*)(A + (size_t)(row0 + r) * FEAT + c4);
        *(float4*)&xs[r][c4] = v;
    }

    float acc[8][8];
    #pragma unroll
    for (int i = 0; i < 8; i++)
        #pragma unroll
        for (int j = 0; j < 8; j++) acc[i][j] = 0.f;

    for (int kk = 0; kk < 4; kk++) {
        __syncthreads();
        #pragma unroll
        for (int i = 0; i < 8; i++) {
            int f4 = tid + i * 128;             // 0..1023
            int r = f4 >> 5, c4 = (f4 & 31) << 2;
            *(float4*)&ws[r][c4] = *(const float4*)(W + (size_t)(kk * 32 + r) * FEAT + c4);
        }
        __syncthreads();
        #pragma unroll
        for (int k = 0; k < 32; k++) {
            float a[8], b[8];
            #pragma unroll
            for (int i = 0; i < 8; i++) a[i] = xs[ty * 8 + i][kk * 32 + k];
            #pragma unroll
            for (int j = 0; j < 8; j++) b[j] = ws[k][tx * 8 + j];
            #pragma unroll
            for (int i = 0; i < 8; i++)
                #pragma unroll
                for (int j = 0; j < 8; j++) acc[i][j] = fmaf(a[i], b[j], acc[i][j]);
        }
    }

    #pragma unroll
    for (int i = 0; i < 8; i++) {
        int r = row0 + ty * 8 + i;
        if (r >= nrows) continue;
        float* Cp = C + (size_t)r * FEAT + tx * 8;
        #pragma unroll
        for (int j = 0; j < 8; j++) {
            float v = acc[i][j];
            if (bias) v += bias[tx * 8 + j];
            Cp[j] = v;
        }
    }
}

// ---------------- attention scores: el/er per node --------------------------
// one warp per node; 256 threads -> 8 nodes/block
template <int HEADS>
__global__ void __launch_bounds__(256) attn_kernel(
    const float* __restrict__ f, const float* __restrict__ al,
    const float* __restrict__ ar, float* __restrict__ el, float* __restrict__ er)
{
    int n = blockIdx.x * 8 + (threadIdx.x >> 5);
    if (n >= N_NODES) return;
    int lane = threadIdx.x & 31;
    const int D = FEAT / HEADS;          // per-head dim
    int d0 = lane * 4;
    int h = d0 / D;
    int dd = d0 - h * D;

    float4 v = *(const float4*)(f + (size_t)n * FEAT + d0);
    const float* alh = al + h * D + dd;
    const float* arh = ar + h * D + dd;
    float pl = v.x * alh[0] + v.y * alh[1] + v.z * alh[2] + v.w * alh[3];
    float pr = v.x * arh[0] + v.y * arh[1] + v.z * arh[2] + v.w * arh[3];

    const int GRP = 32 / HEADS;
    #pragma unroll
    for (int off = GRP / 2; off > 0; off >>= 1) {
        pl += __shfl_xor_sync(0xffffffffu, pl, off);
        pr += __shfl_xor_sync(0xffffffffu, pr, off);
    }
    if ((lane & (GRP - 1)) == 0) {
        el[n * HEADS + h] = pl;
        er[n * HEADS + h] = pr;
    }
}

// ---------------- fused GAT aggregation + epilogue --------------------------
// one warp per destination node. Online softmax over incoming edges, then
// edge-serial gather-accumulate of f[src]*alpha, then bias (+residuals) +
// LayerNorm (+ELU), fully in registers.
__device__ __forceinline__ float leaky02(float x) {
    return x > 0.f ? x : 0.2f * x;
}

template <int HEADS, bool ELU, bool RES>
__global__ void __launch_bounds__(256) aggregate_kernel(
    const float* __restrict__ f, const float* __restrict__ el,
    const float* __restrict__ er, const float* __restrict__ bias,
    const float* __restrict__ gamma, const float* __restrict__ beta,
    const float* __restrict__ add1, const float* __restrict__ add2,
    float* __restrict__ out)
{
    int d = blockIdx.x * 8 + (threadIdx.x >> 5);
    if (d >= N_NODES) return;
    int lane = threadIdx.x & 31;
    const int D = FEAT / HEADS;
    const int hh = (lane * 4) / D;       // head owned by this lane in phase 2

    int start = g_rowptr[d];
    int end   = g_rowptr[d + 1];

    float erd[HEADS];
    #pragma unroll
    for (int h = 0; h < HEADS; h++) erd[h] = er[d * HEADS + h];

    // ---- phase 1: online softmax stats (lane-per-edge) ----
    float mx[HEADS], sm[HEADS];
    #pragma unroll
    for (int h = 0; h < HEADS; h++) { mx[h] = -INFINITY; sm[h] = 0.f; }

    for (int j = start + lane; j < end; j += 32) {
        int s = g_ssrc[j];
        #pragma unroll
        for (int h = 0; h < HEADS; h++) {
            float e = leaky02(el[s * HEADS + h] + erd[h]);
            float nm = fmaxf(mx[h], e);
            sm[h] = sm[h] * __expf(mx[h] - nm) + __expf(e - nm);
            mx[h] = nm;
        }
    }
    // warp merge
    #pragma unroll
    for (int h = 0; h < HEADS; h++) {
        #pragma unroll
        for (int off = 16; off > 0; off >>= 1) {
            float om = __shfl_xor_sync(0xffffffffu, mx[h], off);
            float os = __shfl_xor_sync(0xffffffffu, sm[h], off);
            float nm = fmaxf(mx[h], om);
            float wa = (mx[h] == -INFINITY) ? 0.f : __expf(mx[h] - nm);
            float wb = (om    == -INFINITY) ? 0.f : __expf(om - nm);
            sm[h] = sm[h] * wa + os * wb;
            mx[h] = nm;
        }
    }

    float m_my  = mx[hh];
    float inv_my = (sm[hh] > 0.f) ? (1.f / sm[hh]) : 0.f;
    float er_my = erd[hh];

    // ---- phase 2: edge-serial accumulate (lane-per-feature float4) ----
    float4 acc = make_float4(0.f, 0.f, 0.f, 0.f);
    for (int j = start; j < end; j++) {
        int s = g_ssrc[j];
        float e = leaky02(el[s * HEADS + hh] + er_my);
        float w = __expf(e - m_my) * inv_my;
        float4 v = *(const float4*)(f + (size_t)s * FEAT + lane * 4);
        acc.x = fmaf(w, v.x, acc.x);
        acc.y = fmaf(w, v.y, acc.y);
        acc.z = fmaf(w, v.z, acc.z);
        acc.w = fmaf(w, v.w, acc.w);
    }

    // ---- epilogue: + bias (+residuals), LayerNorm, (ELU) ----
    size_t idx = (size_t)d * FEAT + lane * 4;
    float4 bb = *(const float4*)(bias + lane * 4);
    float4 x = make_float4(acc.x + bb.x, acc.y + bb.y, acc.z + bb.z, acc.w + bb.w);
    if (RES) {
        float4 a1 = *(const float4*)(add1 + idx);
        float4 a2 = *(const float4*)(add2 + idx);
        x.x += a1.x + a2.x; x.y += a1.y + a2.y;
        x.z += a1.z + a2.z; x.w += a1.w + a2.w;
    }

    float s4 = x.x + x.y + x.z + x.w;
    #pragma unroll
    for (int off = 16; off > 0; off >>= 1) s4 += __shfl_xor_sync(0xffffffffu, s4, off);
    float mean = s4 * (1.f / FEAT);

    float dx = x.x - mean, dy = x.y - mean, dz = x.z - mean, dw = x.w - mean;
    float q = dx * dx + dy * dy + dz * dz + dw * dw;
    #pragma unroll
    for (int off = 16; off > 0; off >>= 1) q += __shfl_xor_sync(0xffffffffu, q, off);
    float rs = rsqrtf(q * (1.f / FEAT) + 1e-5f);

    float4 gg = *(const float4*)(gamma + lane * 4);
    float4 be = *(const float4*)(beta + lane * 4);
    float4 y;
    y.x = dx * rs * gg.x + be.x;
    y.y = dy * rs * gg.y + be.y;
    y.z = dz * rs * gg.z + be.z;
    y.w = dw * rs * gg.w + be.w;
    if (ELU) {
        y.x = y.x > 0.f ? y.x : (__expf(y.x) - 1.f);
        y.y = y.y > 0.f ? y.y : (__expf(y.y) - 1.f);
        y.z = y.z > 0.f ? y.z : (__expf(y.z) - 1.f);
        y.w = y.w > 0.f ? y.w : (__expf(y.w) - 1.f);
    }
    *(float4*)(out + idx) = y;
}

// ---------------- launch ----------------------------------------------------
extern "C" void kernel_launch(void* const* d_in, const int* in_sizes, int n_in,
                              void* d_out, int out_size)
{
    const float* x   = (const float*)d_in[0];
    const int*   src = (const int*)  d_in[1];
    const int*   dst = (const int*)  d_in[2];
    const float* W1  = (const float*)d_in[3];
    const float* al1 = (const float*)d_in[4];
    const float* ar1 = (const float*)d_in[5];
    const float* b1  = (const float*)d_in[6];
    const float* W2  = (const float*)d_in[7];
    const float* al2 = (const float*)d_in[8];
    const float* ar2 = (const float*)d_in[9];
    const float* b2  = (const float*)d_in[10];
    const float* Wp  = (const float*)d_in[11];
    const float* bp  = (const float*)d_in[12];
    const float* g1  = (const float*)d_in[13];
    const float* be1 = (const float*)d_in[14];
    const float* g2  = (const float*)d_in[15];
    const float* be2 = (const float*)d_in[16];
    float* out = (float*)d_out;

    float *f1, *f2, *h, *hres, *el1, *er1, *el2, *er2;
    cudaGetSymbolAddress((void**)&f1,   g_f1);
    cudaGetSymbolAddress((void**)&f2,   g_f2);
    cudaGetSymbolAddress((void**)&h,    g_h);
    cudaGetSymbolAddress((void**)&hres, g_hres);
    cudaGetSymbolAddress((void**)&el1,  g_el1);
    cudaGetSymbolAddress((void**)&er1,  g_er1);
    cudaGetSymbolAddress((void**)&el2,  g_el2);
    cudaGetSymbolAddress((void**)&er2,  g_er2);

    const int EB = (N_EDGES + 255) / 256;
    const int NB = (N_NODES + 255) / 256;
    const int GB = (N_NODES + 63) / 64;
    const int WB = N_NODES / 8;          // 6250 (exact)

    // CSR build (topology identical each replay -> deterministic)
    zero_cnt_kernel<<<NB, 256>>>();
    count_kernel<<<EB, 256>>>(dst);
    scan_kernel<<<1, 1024>>>();
    fill_kernel<<<EB, 256>>>(src, dst);

    // GEMMs
    gemm128_kernel<<<GB, 128>>>(x, W1, nullptr, f1, N_NODES);
    gemm128_kernel<<<GB, 128>>>(x, Wp, bp, hres, N_NODES);

    // Layer 1
    attn_kernel<2><<<WB, 256>>>(f1, al1, ar1, el1, er1);
    aggregate_kernel<2, true, false><<<WB, 256>>>(f1, el1, er1, b1, g1, be1,
                                                  nullptr, nullptr, h);

    // Layer 2
    gemm128_kernel<<<GB, 128>>>(h, W2, nullptr, f2, N_NODES);
    attn_kernel<1><<<WB, 256>>>(f2, al2, ar2, el2, er2);
    aggregate_kernel<1, false, true><<<WB, 256>>>(f2, el2, er2, b2, g2, be2,
                                                  h, hres, out);
}

// round 2
// speedup vs baseline: 1.2200x; 1.2200x over previous
#include <cuda_runtime.h>
#include <cuda_bf16.h>
#include <math.h>
#include <stdint.h>

#define N_NODES 50000
#define N_EDGES 800000
#define FEAT 128

// ---------------- scratch (device globals: no allocations allowed) ----------
__device__ float g_f1[N_NODES * FEAT];     // x @ W1
__device__ float g_hres[N_NODES * FEAT];   // x @ Wp + bp
__device__ float g_h[N_NODES * FEAT];      // layer-1 output
__device__ float g_f2[N_NODES * FEAT];     // h @ W2
__device__ float g_el1[N_NODES * 2];
__device__ float g_er1[N_NODES * 2];
__device__ float g_el2[N_NODES];
__device__ float g_er2[N_NODES];
__device__ int   g_rowptr[N_NODES + 1];
__device__ int   g_cnt[N_NODES];
__device__ int   g_ssrc[N_EDGES];          // src ids sorted by dst

// ---------------- CSR build -------------------------------------------------
__global__ void zero_cnt_kernel() {
    int i = blockIdx.x * blockDim.x + threadIdx.x;
    if (i < N_NODES) g_cnt[i] = 0;
}

__global__ void count_kernel(const int* __restrict__ dst) {
    int e = blockIdx.x * blockDim.x + threadIdx.x;
    if (e < N_EDGES) atomicAdd(&g_cnt[dst[e]], 1);
}

__global__ void scan_kernel() {
    __shared__ int sh[1024];
    const int t = threadIdx.x;
    const int CH = (N_NODES + 1023) / 1024;   // 49
    int base = t * CH;
    int s = 0;
    for (int i = 0; i < CH; i++) {
        int idx = base + i;
        if (idx < N_NODES) s += g_cnt[idx];
    }
    sh[t] = s;
    __syncthreads();
    for (int off = 1; off < 1024; off <<= 1) {
        int v = (t >= off) ? sh[t - off] : 0;
        __syncthreads();
        sh[t] += v;
        __syncthreads();
    }
    int run = sh[t] - s;      // exclusive prefix
    for (int i = 0; i < CH; i++) {
        int idx = base + i;
        if (idx < N_NODES) {
            g_rowptr[idx] = run;
            run += g_cnt[idx];
            g_cnt[idx] = 0;   // reset -> cursor for fill_kernel
        }
    }
    if (t == 1023) g_rowptr[N_NODES] = sh[1023];
}

__global__ void fill_kernel(const int* __restrict__ src, const int* __restrict__ dst) {
    int e = blockIdx.x * blockDim.x + threadIdx.x;
    if (e < N_EDGES) {
        int d = dst[e];
        int pos = g_rowptr[d] + atomicAdd(&g_cnt[d], 1);
        g_ssrc[pos] = src[e];
    }
}

// ---------------- TF32 tensor-core GEMM (3xTF32 for ~fp32 accuracy) ---------
// C[n,128] = A[n,128] @ W[128,128] (+bias)
// Block: 256 threads (8 warps), tile 64(M) x 128(N), K-chunk 16.
// Warp grid 2(m) x 4(n); warp tile m32 x n32 via mma.m16n8k8.

__device__ __forceinline__ uint32_t f2tf32(float v) {
    uint32_t r;
    asm("cvt.rna.tf32.f32 %0, %1;" : "=r"(r) : "f"(v));
    return r;
}

__device__ __forceinline__ void split1(float v, uint32_t& hi, uint32_t& lo) {
    hi = f2tf32(v);
    lo = f2tf32(v - __uint_as_float(hi));
}

__device__ __forceinline__ void mma_tf32(float4& c,
    uint32_t a0, uint32_t a1, uint32_t a2, uint32_t a3,
    uint32_t b0, uint32_t b1)
{
    asm("mma.sync.aligned.m16n8k8.row.col.f32.tf32.tf32.f32 "
        "{%0,%1,%2,%3}, {%4,%5,%6,%7}, {%8,%9}, {%0,%1,%2,%3};"
        : "+f"(c.x), "+f"(c.y), "+f"(c.z), "+f"(c.w)
        : "r"(a0), "r"(a1), "r"(a2), "r"(a3), "r"(b0), "r"(b1));
}

#define AS_STR 20    // 16 + 4 pad : frag LDS bank-free ((4r+k)%32 all distinct)
#define WS_STR 136   // 128 + 8 pad: frag LDS bank-free ((8k+n)%32 all distinct)

__global__ void __launch_bounds__(256) gemm_tc_kernel(
    const float* __restrict__ A, const float* __restrict__ W,
    const float* __restrict__ bias, float* __restrict__ C, int nrows)
{
    __shared__ uint32_t As_hi[64 * AS_STR];
    __shared__ uint32_t As_lo[64 * AS_STR];
    __shared__ uint32_t Ws_hi[16 * WS_STR];
    __shared__ uint32_t Ws_lo[16 * WS_STR];

    const int tid  = threadIdx.x;
    const int wid  = tid >> 5;
    const int lane = tid & 31;
    const int g    = lane >> 2;     // group 0..7
    const int t4   = lane & 3;      // 0..3
    const int warp_m = wid >> 2;    // 0..1
    const int warp_n = wid & 3;     // 0..3
    const int row0 = blockIdx.x * 64;

    float4 acc[2][4];
    #pragma unroll
    for (int mt = 0; mt < 2; mt++)
        #pragma unroll
        for (int nt = 0; nt < 4; nt++)
            acc[mt][nt] = make_float4(0.f, 0.f, 0.f, 0.f);

    for (int kk = 0; kk < 8; kk++) {
        __syncthreads();
        // stage A chunk: 64 rows x 16 cols -> 256 float4 (1/thread)
        {
            int r  = tid >> 2;
            int c4 = (tid & 3) << 2;
            float4 v = make_float4(0.f, 0.f, 0.f, 0.f);
            if (row0 + r < nrows)
                v = *(const float4*)(A + (size_t)(row0 + r) * FEAT + kk * 16 + c4);
            uint4 hi, lo;
            split1(v.x, hi.x, lo.x); split1(v.y, hi.y, lo.y);
            split1(v.z, hi.z, lo.z); split1(v.w, hi.w, lo.w);
            *(uint4*)&As_hi[r * AS_STR + c4] = hi;
            *(uint4*)&As_lo[r * AS_STR + c4] = lo;
        }
        // stage W chunk: 16 rows x 128 cols -> 512 float4 (2/thread)
        #pragma unroll
        for (int i = 0; i < 2; i++) {
            int f4 = tid + i * 256;
            int k  = f4 >> 5;
            int c4 = (f4 & 31) << 2;
            float4 v = *(const float4*)(W + (size_t)(kk * 16 + k) * FEAT + c4);
            uint4 hi, lo;
            split1(v.x, hi.x, lo.x); split1(v.y, hi.y, lo.y);
            split1(v.z, hi.z, lo.z); split1(v.w, hi.w, lo.w);
            *(uint4*)&Ws_hi[k * WS_STR + c4] = hi;
            *(uint4*)&Ws_lo[k * WS_STR + c4] = lo;
        }
        __syncthreads();

        #pragma unroll
        for (int k8 = 0; k8 < 2; k8++) {
            const int kb = k8 * 8;
            uint32_t ah[2][4], al[2][4];
            #pragma unroll
            for (int mt = 0; mt < 2; mt++) {
                int r0 = (warp_m * 32 + mt * 16 + g) * AS_STR;
                int r1 = r0 + 8 * AS_STR;
                ah[mt][0] = As_hi[r0 + kb + t4];
                ah[mt][1] = As_hi[r1 + kb + t4];
                ah[mt][2] = As_hi[r0 + kb + t4 + 4];
                ah[mt][3] = As_hi[r1 + kb + t4 + 4];
                al[mt][0] = As_lo[r0 + kb + t4];
                al[mt][1] = As_lo[r1 + kb + t4];
                al[mt][2] = As_lo[r0 + kb + t4 + 4];
                al[mt][3] = As_lo[r1 + kb + t4 + 4];
            }
            #pragma unroll
            for (int nt = 0; nt < 4; nt++) {
                int nb = warp_n * 32 + nt * 8 + g;
                uint32_t bh0 = Ws_hi[(kb + t4) * WS_STR + nb];
                uint32_t bh1 = Ws_hi[(kb + t4 + 4) * WS_STR + nb];
                uint32_t bl0 = Ws_lo[(kb + t4) * WS_STR + nb];
                uint32_t bl1 = Ws_lo[(kb + t4 + 4) * WS_STR + nb];
                #pragma unroll
                for (int mt = 0; mt < 2; mt++) {
                    mma_tf32(acc[mt][nt], ah[mt][0], ah[mt][1], ah[mt][2], ah[mt][3], bh0, bh1);
                    mma_tf32(acc[mt][nt], ah[mt][0], ah[mt][1], ah[mt][2], ah[mt][3], bl0, bl1);
                    mma_tf32(acc[mt][nt], al[mt][0], al[mt][1], al[mt][2], al[mt][3], bh0, bh1);
                }
            }
        }
    }

    // epilogue
    #pragma unroll
    for (int mt = 0; mt < 2; mt++) {
        int row = row0 + warp_m * 32 + mt * 16 + g;
        #pragma unroll
        for (int nt = 0; nt < 4; nt++) {
            int col = warp_n * 32 + nt * 8 + 2 * t4;
            float bx = 0.f, by = 0.f;
            if (bias) { bx = bias[col]; by = bias[col + 1]; }
            float4 c = acc[mt][nt];
            if (row < nrows) {
                float2 v = make_float2(c.x + bx, c.y + by);
                *(float2*)(C + (size_t)row * FEAT + col) = v;
            }
            if (row + 8 < nrows) {
                float2 v = make_float2(c.z + bx, c.w + by);
                *(float2*)(C + (size_t)(row + 8) * FEAT + col) = v;
            }
        }
    }
}

// ---------------- attention scores: el/er per node --------------------------
template <int HEADS>
__global__ void __launch_bounds__(256) attn_kernel(
    const float* __restrict__ f, const float* __restrict__ al,
    const float* __restrict__ ar, float* __restrict__ el, float* __restrict__ er)
{
    int n = blockIdx.x * 8 + (threadIdx.x >> 5);
    if (n >= N_NODES) return;
    int lane = threadIdx.x & 31;
    const int D = FEAT / HEADS;
    int d0 = lane * 4;
    int h = d0 / D;
    int dd = d0 - h * D;

    float4 v = *(const float4*)(f + (size_t)n * FEAT + d0);
    const float* alh = al + h * D + dd;
    const float* arh = ar + h * D + dd;
    float pl = v.x * alh[0] + v.y * alh[1] + v.z * alh[2] + v.w * alh[3];
    float pr = v.x * arh[0] + v.y * arh[1] + v.z * arh[2] + v.w * arh[3];

    const int GRP = 32 / HEADS;
    #pragma unroll
    for (int off = GRP / 2; off > 0; off >>= 1) {
        pl += __shfl_xor_sync(0xffffffffu, pl, off);
        pr += __shfl_xor_sync(0xffffffffu, pr, off);
    }
    if ((lane & (GRP - 1)) == 0) {
        el[n * HEADS + h] = pl;
        er[n * HEADS + h] = pr;
    }
}

// ---------------- fused GAT aggregation + epilogue --------------------------
__device__ __forceinline__ float leaky02(float x) {
    return x > 0.f ? x : 0.2f * x;
}

template <int HEADS, bool ELU, bool RES>
__global__ void __launch_bounds__(256) aggregate_kernel(
    const float* __restrict__ f, const float* __restrict__ el,
    const float* __restrict__ er, const float* __restrict__ bias,
    const float* __restrict__ gamma, const float* __restrict__ beta,
    const float* __restrict__ add1, const float* __restrict__ add2,
    float* __restrict__ out)
{
    int d = blockIdx.x * 8 + (threadIdx.x >> 5);
    if (d >= N_NODES) return;
    int lane = threadIdx.x & 31;
    const int D = FEAT / HEADS;
    const int hh = (lane * 4) / D;

    int start = g_rowptr[d];
    int end   = g_rowptr[d + 1];

    float erd[HEADS];
    #pragma unroll
    for (int h = 0; h < HEADS; h++) erd[h] = er[d * HEADS + h];

    // ---- phase 1: online softmax stats (lane-per-edge) ----
    float mx[HEADS], sm[HEADS];
    #pragma unroll
    for (int h = 0; h < HEADS; h++) { mx[h] = -INFINITY; sm[h] = 0.f; }

    for (int j = start + lane; j < end; j += 32) {
        int s = g_ssrc[j];
        if (HEADS == 2) {
            float2 ev = *(const float2*)(el + s * 2);
            float e0 = leaky02(ev.x + erd[0]);
            float e1 = leaky02(ev.y + erd[1]);
            float nm0 = fmaxf(mx[0], e0);
            sm[0] = sm[0] * __expf(mx[0] - nm0) + __expf(e0 - nm0);
            mx[0] = nm0;
            float nm1 = fmaxf(mx[1], e1);
            sm[1] = sm[1] * __expf(mx[1] - nm1) + __expf(e1 - nm1);
            mx[1] = nm1;
        } else {
            float e = leaky02(el[s] + erd[0]);
            float nm = fmaxf(mx[0], e);
            sm[0] = sm[0] * __expf(mx[0] - nm) + __expf(e - nm);
            mx[0] = nm;
        }
    }
    #pragma unroll
    for (int h = 0; h < HEADS; h++) {
        #pragma unroll
        for (int off = 16; off > 0; off >>= 1) {
            float om = __shfl_xor_sync(0xffffffffu, mx[h], off);
            float os = __shfl_xor_sync(0xffffffffu, sm[h], off);
            float nm = fmaxf(mx[h], om);
            float wa = (mx[h] == -INFINITY) ? 0.f : __expf(mx[h] - nm);
            float wb = (om    == -INFINITY) ? 0.f : __expf(om - nm);
            sm[h] = sm[h] * wa + os * wb;
            mx[h] = nm;
        }
    }

    float m_my   = mx[hh];
    float inv_my = (sm[hh] > 0.f) ? (1.f / sm[hh]) : 0.f;
    float er_my  = erd[hh];

    // ---- phase 2: edge-serial accumulate, 2x unrolled for MLP ----
    float4 acc = make_float4(0.f, 0.f, 0.f, 0.f);
    int j = start;
    for (; j + 1 < end; j += 2) {
        int s0 = g_ssrc[j];
        int s1 = g_ssrc[j + 1];
        float e0 = leaky02(el[s0 * HEADS + hh] + er_my);
        float e1 = leaky02(el[s1 * HEADS + hh] + er_my);
        float4 v0 = *(const float4*)(f + (size_t)s0 * FEAT + lane * 4);
        float4 v1 = *(const float4*)(f + (size_t)s1 * FEAT + lane * 4);
        float w0 = __expf(e0 - m_my) * inv_my;
        float w1 = __expf(e1 - m_my) * inv_my;
        acc.x = fmaf(w0, v0.x, acc.x); acc.x = fmaf(w1, v1.x, acc.x);
        acc.y = fmaf(w0, v0.y, acc.y); acc.y = fmaf(w1, v1.y, acc.y);
        acc.z = fmaf(w0, v0.z, acc.z); acc.z = fmaf(w1, v1.z, acc.z);
        acc.w = fmaf(w0, v0.w, acc.w); acc.w = fmaf(w1, v1.w, acc.w);
    }
    if (j < end) {
        int s = g_ssrc[j];
        float e = leaky02(el[s * HEADS + hh] + er_my);
        float w = __expf(e - m_my) * inv_my;
        float4 v = *(const float4*)(f + (size_t)s * FEAT + lane * 4);
        acc.x = fmaf(w, v.x, acc.x);
        acc.y = fmaf(w, v.y, acc.y);
        acc.z = fmaf(w, v.z, acc.z);
        acc.w = fmaf(w, v.w, acc.w);
    }

    // ---- epilogue: + bias (+residuals), LayerNorm, (ELU) ----
    size_t idx = (size_t)d * FEAT + lane * 4;
    float4 bb = *(const float4*)(bias + lane * 4);
    float4 x = make_float4(acc.x + bb.x, acc.y + bb.y, acc.z + bb.z, acc.w + bb.w);
    if (RES) {
        float4 a1 = *(const float4*)(add1 + idx);
        float4 a2 = *(const float4*)(add2 + idx);
        x.x += a1.x + a2.x; x.y += a1.y + a2.y;
        x.z += a1.z + a2.z; x.w += a1.w + a2.w;
    }

    float s4 = x.x + x.y + x.z + x.w;
    #pragma unroll
    for (int off = 16; off > 0; off >>= 1) s4 += __shfl_xor_sync(0xffffffffu, s4, off);
    float mean = s4 * (1.f / FEAT);

    float dx = x.x - mean, dy = x.y - mean, dz = x.z - mean, dw = x.w - mean;
    float q = dx * dx + dy * dy + dz * dz + dw * dw;
    #pragma unroll
    for (int off = 16; off > 0; off >>= 1) q += __shfl_xor_sync(0xffffffffu, q, off);
    float rs = rsqrtf(q * (1.f / FEAT) + 1e-5f);

    float4 gg = *(const float4*)(gamma + lane * 4);
    float4 be = *(const float4*)(beta + lane * 4);
    float4 y;
    y.x = dx * rs * gg.x + be.x;
    y.y = dy * rs * gg.y + be.y;
    y.z = dz * rs * gg.z + be.z;
    y.w = dw * rs * gg.w + be.w;
    if (ELU) {
        y.x = y.x > 0.f ? y.x : (__expf(y.x) - 1.f);
        y.y = y.y > 0.f ? y.y : (__expf(y.y) - 1.f);
        y.z = y.z > 0.f ? y.z : (__expf(y.z) - 1.f);
        y.w = y.w > 0.f ? y.w : (__expf(y.w) - 1.f);
    }
    *(float4*)(out + idx) = y;
}

// ---------------- launch ----------------------------------------------------
extern "C" void kernel_launch(void* const* d_in, const int* in_sizes, int n_in,
                              void* d_out, int out_size)
{
    const float* x   = (const float*)d_in[0];
    const int*   src = (const int*)  d_in[1];
    const int*   dst = (const int*)  d_in[2];
    const float* W1  = (const float*)d_in[3];
    const float* al1 = (const float*)d_in[4];
    const float* ar1 = (const float*)d_in[5];
    const float* b1  = (const float*)d_in[6];
    const float* W2  = (const float*)d_in[7];
    const float* al2 = (const float*)d_in[8];
    const float* ar2 = (const float*)d_in[9];
    const float* b2  = (const float*)d_in[10];
    const float* Wp  = (const float*)d_in[11];
    const float* bp  = (const float*)d_in[12];
    const float* g1  = (const float*)d_in[13];
    const float* be1 = (const float*)d_in[14];
    const float* g2  = (const float*)d_in[15];
    const float* be2 = (const float*)d_in[16];
    float* out = (float*)d_out;

    float *f1, *f2, *h, *hres, *el1, *er1, *el2, *er2;
    cudaGetSymbolAddress((void**)&f1,   g_f1);
    cudaGetSymbolAddress((void**)&f2,   g_f2);
    cudaGetSymbolAddress((void**)&h,    g_h);
    cudaGetSymbolAddress((void**)&hres, g_hres);
    cudaGetSymbolAddress((void**)&el1,  g_el1);
    cudaGetSymbolAddress((void**)&er1,  g_er1);
    cudaGetSymbolAddress((void**)&el2,  g_el2);
    cudaGetSymbolAddress((void**)&er2,  g_er2);

    const int EB = (N_EDGES + 255) / 256;
    const int NB = (N_NODES + 255) / 256;
    const int GB = (N_NODES + 63) / 64;   // 782
    const int WB = N_NODES / 8;           // 6250 (exact)

    // CSR build (topology identical each replay -> deterministic)
    zero_cnt_kernel<<<NB, 256>>>();
    count_kernel<<<EB, 256>>>(dst);
    scan_kernel<<<1, 1024>>>();
    fill_kernel<<<EB, 256>>>(src, dst);

    // GEMMs (tensor cores, 3xTF32)
    gemm_tc_kernel<<<GB, 256>>>(x, W1, nullptr, f1, N_NODES);
    gemm_tc_kernel<<<GB, 256>>>(x, Wp, bp, hres, N_NODES);

    // Layer 1
    attn_kernel<2><<<WB, 256>>>(f1, al1, ar1, el1, er1);
    aggregate_kernel<2, true, false><<<WB, 256>>>(f1, el1, er1, b1, g1, be1,
                                                  nullptr, nullptr, h);

    // Layer 2
    gemm_tc_kernel<<<GB, 256>>>(h, W2, nullptr, f2, N_NODES);
    attn_kernel<1><<<WB, 256>>>(f2, al2, ar2, el2, er2);
    aggregate_kernel<1, false, true><<<WB, 256>>>(f2, el2, er2, b2, g2, be2,
                                                  h, hres, out);
}